// round 1
// baseline (speedup 1.0000x reference)
#include <cuda_runtime.h>
#include <math.h>

#define BDIM 4
#define TDIM 8192
#define CDIM 1024
#define EDIM 64
#define NTOK (BDIM*TDIM)      // 32768 tokens
#define KTOP 2

// -------- device scratch (no allocations allowed) --------
__device__ float        g_M1T[CDIM*EDIM];     // folded weights, [d][e]
__device__ float        g_hcond[BDIM*CDIM];   // cond @ Wc[:,C:]^T
__device__ float        g_bias[BDIM*EDIM];    // hcond @ Wg^T
__device__ float        g_imp_parts[8][EDIM];
__device__ unsigned int g_cnt_parts[8][EDIM];

// -------- zero scratch --------
__global__ void zero_kernel() {
    int i = blockIdx.x * blockDim.x + threadIdx.x;
    if (i < CDIM*EDIM) g_M1T[i] = 0.0f;
    if (i < 8*EDIM) {
        (&g_imp_parts[0][0])[i] = 0.0f;
        (&g_cnt_parts[0][0])[i] = 0u;
    }
}

// -------- hcond[b][c] = sum_d cond[b][d] * Wc[c][C+d] --------
__global__ void hcond_kernel(const float* __restrict__ cond,
                             const float* __restrict__ Wc) {
    int warp = (blockIdx.x * blockDim.x + threadIdx.x) >> 5;
    int lane = threadIdx.x & 31;
    if (warp >= BDIM*CDIM) return;
    int b = warp >> 10;
    int c = warp & (CDIM-1);
    const float* crow = cond + b * CDIM;
    const float* wrow = Wc + (size_t)c * (2*CDIM) + CDIM;
    float acc = 0.0f;
    for (int d = lane; d < CDIM; d += 32)
        acc = fmaf(crow[d], wrow[d], acc);
    #pragma unroll
    for (int off = 16; off; off >>= 1)
        acc += __shfl_xor_sync(0xffffffffu, acc, off);
    if (lane == 0) g_hcond[b*CDIM + c] = acc;
}

// -------- bias[b][e] = sum_c hcond[b][c] * Wg[e][c] --------
__global__ void bias_kernel(const float* __restrict__ Wg) {
    int warp = (blockIdx.x * blockDim.x + threadIdx.x) >> 5;
    int lane = threadIdx.x & 31;
    if (warp >= BDIM*EDIM) return;
    int b = warp >> 6;
    int e = warp & (EDIM-1);
    const float* h = g_hcond + b * CDIM;
    const float* w = Wg + (size_t)e * CDIM;
    float acc = 0.0f;
    for (int c = lane; c < CDIM; c += 32)
        acc = fmaf(h[c], w[c], acc);
    #pragma unroll
    for (int off = 16; off; off >>= 1)
        acc += __shfl_xor_sync(0xffffffffu, acc, off);
    if (lane == 0) g_bias[b*EDIM + e] = acc;
}

// -------- M1T[d][e] = sum_c Wg[e][c] * Wc[c][d],  d < C --------
// grid (16 d-tiles, 8 c-splits), 256 threads, k-split accumulated via atomics.
__global__ __launch_bounds__(256) void m1_kernel(const float* __restrict__ Wg,
                                                 const float* __restrict__ Wc) {
    __shared__ float sWgT[64][68];  // [c][e]
    __shared__ float sWc [64][68];  // [c][d]
    int d0    = blockIdx.x * 64;
    int cbase = blockIdx.y * 128;
    int tid   = threadIdx.x;
    int ex = (tid & 15) * 4;        // 4 experts
    int dx = (tid >> 4) * 4;        // 4 d-columns

    float acc[4][4] = {};
    for (int cc = 0; cc < 128; cc += 64) {
        int c0 = cbase + cc;
        {   // Wg chunk, transposed into smem
            int e = tid >> 2;
            int j = (tid & 3) * 16;
            const float* src = Wg + (size_t)e * CDIM + c0 + j;
            #pragma unroll
            for (int i = 0; i < 16; i += 4) {
                float4 v = *(const float4*)(src + i);
                sWgT[j+i+0][e] = v.x; sWgT[j+i+1][e] = v.y;
                sWgT[j+i+2][e] = v.z; sWgT[j+i+3][e] = v.w;
            }
        }
        {   // Wc chunk, direct copy
            int c = tid >> 2;
            int j = (tid & 3) * 16;
            const float* src = Wc + (size_t)(c0 + c) * (2*CDIM) + d0 + j;
            #pragma unroll
            for (int i = 0; i < 16; i += 4)
                *(float4*)&sWc[c][j+i] = *(const float4*)(src + i);
        }
        __syncthreads();
        #pragma unroll 8
        for (int c = 0; c < 64; c++) {
            float4 g = *(const float4*)&sWgT[c][ex];
            float4 w = *(const float4*)&sWc[c][dx];
            float gg[4] = {g.x, g.y, g.z, g.w};
            float ww[4] = {w.x, w.y, w.z, w.w};
            #pragma unroll
            for (int i = 0; i < 4; i++)
                #pragma unroll
                for (int j = 0; j < 4; j++)
                    acc[i][j] = fmaf(gg[i], ww[j], acc[i][j]);
        }
        __syncthreads();
    }
    #pragma unroll
    for (int j = 0; j < 4; j++)
        #pragma unroll
        for (int i = 0; i < 4; i++)
            atomicAdd(&g_M1T[(size_t)(d0 + dx + j) * EDIM + ex + i], acc[i][j]);
}

// -------- main fused kernel: logits GEMM + softmax + top2 + stats --------
// 64 tokens per block, 256 threads, full E=64.
__global__ __launch_bounds__(256) void router_main(const float* __restrict__ x,
                                                   float* __restrict__ out) {
    __shared__ float sx[64][76];   // x tile [t][k] (pad 76: bank-safe broadcast)
    __shared__ float sm[64][64];   // M1T tile [k][e]
    __shared__ float simp[64];
    __shared__ unsigned scnt[64];

    int tid  = threadIdx.x;
    int tok0 = blockIdx.x * 64;
    int b    = tok0 >> 13;          // token / 8192

    if (tid < 64) { simp[tid] = 0.0f; scnt[tid] = 0u; }

    int te = (tid & 15) * 4;        // 4 experts (coalesced LDS.128 on sm)
    int tx = (tid >> 4) * 4;        // 4 tokens  (broadcast LDS on sx)
    float acc[4][4] = {};           // [token][expert]

    int lt = tid >> 2;              // loader row 0..63
    int lj = (tid & 3) * 16;        // loader k offset

    for (int k0 = 0; k0 < CDIM; k0 += 64) {
        const float* xsrc = x + (size_t)(tok0 + lt) * CDIM + k0 + lj;
        #pragma unroll
        for (int i = 0; i < 16; i += 4)
            *(float4*)&sx[lt][lj+i] = *(const float4*)(xsrc + i);
        const float* msrc = g_M1T + (size_t)(k0 + lt) * EDIM + lj;
        #pragma unroll
        for (int i = 0; i < 16; i += 4)
            *(float4*)&sm[lt][lj+i] = *(const float4*)(msrc + i);
        __syncthreads();
        #pragma unroll 8
        for (int k = 0; k < 64; k++) {
            float4 m4 = *(const float4*)&sm[k][te];
            float mm[4] = {m4.x, m4.y, m4.z, m4.w};
            #pragma unroll
            for (int i = 0; i < 4; i++) {
                float xv = sx[tx+i][k];
                #pragma unroll
                for (int j = 0; j < 4; j++)
                    acc[i][j] = fmaf(xv, mm[j], acc[i][j]);
            }
        }
        __syncthreads();
    }

    // logits (+bias) into smem, reuse sx region
    float (*slog)[76] = sx;
    #pragma unroll
    for (int i = 0; i < 4; i++)
        #pragma unroll
        for (int j = 0; j < 4; j++)
            slog[tx+i][te+j] = acc[i][j] + g_bias[b*EDIM + te + j];
    __syncthreads();

    // epilogue: each warp handles 8 tokens; lane covers experts {l, l+32}
    int warp = tid >> 5, lane = tid & 31;
    float* out_idx = out;
    float* out_sc  = out + (size_t)NTOK * KTOP;
    float* out_pr  = out + (size_t)2 * NTOK * KTOP;
    const float NEG_INF = __int_as_float(0xff800000);

    float impL0 = 0.0f, impL1 = 0.0f;
    for (int tt = warp * 8; tt < warp * 8 + 8; tt++) {
        float v0 = slog[tt][lane];
        float v1 = slog[tt][lane + 32];
        // softmax over 64
        float m = fmaxf(v0, v1);
        #pragma unroll
        for (int off = 16; off; off >>= 1)
            m = fmaxf(m, __shfl_xor_sync(0xffffffffu, m, off));
        float e0 = expf(v0 - m), e1 = expf(v1 - m);
        float s = e0 + e1;
        #pragma unroll
        for (int off = 16; off; off >>= 1)
            s += __shfl_xor_sync(0xffffffffu, s, off);
        float inv = 1.0f / s;
        float p0 = e0 * inv, p1 = e1 * inv;
        int gt = tok0 + tt;
        out_pr[(size_t)gt * EDIM + lane]      = p0;
        out_pr[(size_t)gt * EDIM + lane + 32] = p1;
        impL0 += p0; impL1 += p1;

        // top-1 (ties -> lower index, matching jax top_k)
        float rv; int ri;
        if (v0 >= v1) { rv = v0; ri = lane; } else { rv = v1; ri = lane + 32; }
        #pragma unroll
        for (int off = 16; off; off >>= 1) {
            float ov = __shfl_xor_sync(0xffffffffu, rv, off);
            int   oi = __shfl_xor_sync(0xffffffffu, ri, off);
            if (ov > rv || (ov == rv && oi < ri)) { rv = ov; ri = oi; }
        }
        int i1st = ri; float v1st = rv;
        // top-2: mask out the winning slot only
        float c0 = (lane      == i1st) ? NEG_INF : v0;
        float c1 = (lane + 32 == i1st) ? NEG_INF : v1;
        if (c0 >= c1) { rv = c0; ri = lane; } else { rv = c1; ri = lane + 32; }
        #pragma unroll
        for (int off = 16; off; off >>= 1) {
            float ov = __shfl_xor_sync(0xffffffffu, rv, off);
            int   oi = __shfl_xor_sync(0xffffffffu, ri, off);
            if (ov > rv || (ov == rv && oi < ri)) { rv = ov; ri = oi; }
        }
        int i2nd = ri; float v2nd = rv;

        if (lane == 0) {
            float ee = expf(v2nd - v1st);   // softmax over the top-2 pair
            float d  = 1.0f + ee;
            out_idx[gt*2 + 0] = (float)i1st;
            out_idx[gt*2 + 1] = (float)i2nd;
            out_sc [gt*2 + 0] = 1.0f / d;
            out_sc [gt*2 + 1] = ee / d;
            atomicAdd(&scnt[i1st], 1u);
            atomicAdd(&scnt[i2nd], 1u);
        }
    }
    atomicAdd(&simp[lane],      impL0);
    atomicAdd(&simp[lane + 32], impL1);
    __syncthreads();
    if (tid < 64) {
        atomicAdd(&g_imp_parts[blockIdx.x & 7][tid], simp[tid]);
        atomicAdd(&g_cnt_parts[blockIdx.x & 7][tid], scnt[tid]);
    }
}

// -------- finalize importance / load --------
__global__ void finalize_kernel(float* __restrict__ out) {
    int e = threadIdx.x;
    if (e >= EDIM) return;
    float imp = 0.0f;
    unsigned cnt = 0;
    #pragma unroll
    for (int p = 0; p < 8; p++) {
        imp += g_imp_parts[p][e];
        cnt += g_cnt_parts[p][e];
    }
    size_t base = (size_t)2 * NTOK * KTOP + (size_t)NTOK * EDIM;
    out[base + e]        = imp / (float)NTOK;                 // importance
    out[base + EDIM + e] = (float)cnt / (float)(NTOK * KTOP); // load
}

extern "C" void kernel_launch(void* const* d_in, const int* in_sizes, int n_in,
                              void* d_out, int out_size) {
    const float* x    = (const float*)d_in[0];
    const float* cond = (const float*)d_in[1];
    const float* Wg   = (const float*)d_in[2];
    const float* Wc   = (const float*)d_in[3];
    float* out = (float*)d_out;
    (void)in_sizes; (void)n_in; (void)out_size;

    zero_kernel   <<<(CDIM*EDIM + 255) / 256, 256>>>();
    hcond_kernel  <<<(BDIM*CDIM * 32) / 256, 256>>>(cond, Wc);
    bias_kernel   <<<(BDIM*EDIM * 32 + 255) / 256, 256>>>(Wg);
    m1_kernel     <<<dim3(16, 8), 256>>>(Wg, Wc);
    router_main   <<<NTOK / 64, 256>>>(x, out);
    finalize_kernel<<<1, 64>>>(out);
}